// round 12
// baseline (speedup 1.0000x reference)
#include <cuda_runtime.h>
#include <cuda_fp16.h>
#include <mma.h>
#include <cstdint>

using namespace nvcuda;

// Problem constants (match reference)
#define T_STEPS 100
#define BATCH   32
#define NIN     1024
#define NOUT    512
#define K_TOT   3200

#define LR_LTP  1e-4f
#define DECAY      0.951229424500714f    // exp(-1/20)
#define INV_DECAY  1.0512710963760241f   // exp(+1/20)
#define D49        0.0862935864993704f   // exp(-49/20)
#define D50        0.0820849986238988f   // exp(-50/20)

// Device scratch (allocation-free). Referenced ONLY from device code.
__device__ __align__(16) __half g_pre_tr_h [K_TOT * NIN];   // [k, i]
__device__ __align__(16) __half g_post_tr_h[K_TOT * NOUT];  // [k, o]
__device__ __align__(16) __half g_pre_trT [NIN  * K_TOT];   // [i, k]
__device__ __align__(16) __half g_post_trT[NOUT * K_TOT];   // [o, k]
__device__ __align__(16) __half g_pre_sT  [NIN  * K_TOT];   // [i, k] fp16 spikes
__device__ __align__(16) __half g_post_sT [NOUT * K_TOT];   // [o, k]
__device__ __align__(16) float  g_part[4][NOUT * NIN];      // [gemm*2+split][o,i]

// ============================ 1) Traces ====================================
// R10 trace kernel (T chunked in 2 with dot-product carry).
#define PRE_CTAS  ((2 * BATCH * NIN ) / 256)   // 256
#define POST_CTAS ((2 * BATCH * NOUT) / 256)   // 128
#define UB 10

__global__ void __launch_bounds__(256)
traces_fused_kernel(const float* __restrict__ pre_spikes,
                    const float* __restrict__ post_spikes,
                    const float* __restrict__ pre_trace0,
                    const float* __restrict__ post_trace0,
                    float* __restrict__ out_pre_tr,
                    float* __restrict__ out_post_tr)
{
    if (blockIdx.x < PRE_CTAS) {
        const int g   = blockIdx.x * 256 + threadIdx.x;
        const int c   = g >> 15;
        const int idx = g & 32767;               // b*NIN + i
        float tr;
        if (c == 0) {
            tr = pre_trace0[idx];
            for (int t0 = 0; t0 < 50; t0 += UB) {
                float s[UB];
                #pragma unroll
                for (int u = 0; u < UB; ++u)
                    s[u] = __ldcs(&pre_spikes[(t0 + u) * (BATCH * NIN) + idx]);
                #pragma unroll
                for (int u = 0; u < UB; ++u) {
                    tr = tr * DECAY + s[u];
                    g_pre_tr_h[(t0 + u) * (BATCH * NIN) + idx] = __float2half_rn(tr);
                }
            }
        } else {
            float acc0 = 0.f, acc1 = 0.f, w = D49;
            for (int t0 = 0; t0 < 50; t0 += UB) {
                float s[UB];
                #pragma unroll
                for (int u = 0; u < UB; ++u)
                    s[u] = __ldcs(&pre_spikes[(t0 + u) * (BATCH * NIN) + idx]);
                #pragma unroll
                for (int u = 0; u < UB; ++u) {
                    if (u & 1) acc1 = fmaf(w, s[u], acc1);
                    else       acc0 = fmaf(w, s[u], acc0);
                    w *= INV_DECAY;
                }
            }
            tr = fmaf(D50, pre_trace0[idx], acc0 + acc1);
            for (int t0 = 50; t0 < 100; t0 += UB) {
                float s[UB];
                #pragma unroll
                for (int u = 0; u < UB; ++u)
                    s[u] = __ldcs(&pre_spikes[(t0 + u) * (BATCH * NIN) + idx]);
                #pragma unroll
                for (int u = 0; u < UB; ++u) {
                    tr = tr * DECAY + s[u];
                    g_pre_tr_h[(t0 + u) * (BATCH * NIN) + idx] = __float2half_rn(tr);
                }
            }
            out_pre_tr[idx] = tr;
        }
    } else {
        const int g   = (blockIdx.x - PRE_CTAS) * 256 + threadIdx.x;
        const int c   = g >> 14;
        const int idx = g & 16383;               // b*NOUT + o
        float tr;
        if (c == 0) {
            tr = post_trace0[idx];
            for (int t0 = 0; t0 < 50; t0 += UB) {
                float s[UB];
                #pragma unroll
                for (int u = 0; u < UB; ++u)
                    s[u] = __ldcs(&post_spikes[(t0 + u) * (BATCH * NOUT) + idx]);
                #pragma unroll
                for (int u = 0; u < UB; ++u) {
                    tr = tr * DECAY + s[u];
                    g_post_tr_h[(t0 + u) * (BATCH * NOUT) + idx] = __float2half_rn(tr);
                }
            }
        } else {
            float acc0 = 0.f, acc1 = 0.f, w = D49;
            for (int t0 = 0; t0 < 50; t0 += UB) {
                float s[UB];
                #pragma unroll
                for (int u = 0; u < UB; ++u)
                    s[u] = __ldcs(&post_spikes[(t0 + u) * (BATCH * NOUT) + idx]);
                #pragma unroll
                for (int u = 0; u < UB; ++u) {
                    if (u & 1) acc1 = fmaf(w, s[u], acc1);
                    else       acc0 = fmaf(w, s[u], acc0);
                    w *= INV_DECAY;
                }
            }
            tr = fmaf(D50, post_trace0[idx], acc0 + acc1);
            for (int t0 = 50; t0 < 100; t0 += UB) {
                float s[UB];
                #pragma unroll
                for (int u = 0; u < UB; ++u)
                    s[u] = __ldcs(&post_spikes[(t0 + u) * (BATCH * NOUT) + idx]);
                #pragma unroll
                for (int u = 0; u < UB; ++u) {
                    tr = tr * DECAY + s[u];
                    g_post_tr_h[(t0 + u) * (BATCH * NOUT) + idx] = __float2half_rn(tr);
                }
            }
            out_post_tr[idx] = tr;
        }
    }
}

// ============================ 2) Transposes ================================
// 64x64 tiles, [K, C] -> [C, K]. tile[64][66] halves.
__device__ __forceinline__ void transpose_tile_h2h(const __half* __restrict__ in,
                                                   __half* __restrict__ out,
                                                   int C, int kt, int ct)
{
    __shared__ __half tile[64][66];
    const int tid = threadIdx.x;
    {
        const int r  = tid >> 2;
        const int cq = (tid & 3) * 16;
        const __half* src = in + (kt * 64 + r) * C + ct * 64 + cq;
        #pragma unroll
        for (int u = 0; u < 16; u += 2)
            *(uint32_t*)&tile[r][cq + u] = *(const uint32_t*)(src + u);
    }
    __syncthreads();
    {
        const int cc = tid >> 2;
        const int kq = (tid & 3) * 16;
        __half* dst = out + (ct * 64 + cc) * K_TOT + kt * 64 + kq;
        #pragma unroll
        for (int u = 0; u < 16; u += 2) {
            __half2 h = __halves2half2(tile[kq + u][cc], tile[kq + u + 1][cc]);
            *(uint32_t*)(dst + u) = *(uint32_t*)&h;
        }
    }
}

__device__ __forceinline__ void transpose_tile_f2h(const float* __restrict__ in,
                                                   __half* __restrict__ out,
                                                   int C, int kt, int ct)
{
    __shared__ __half tile[64][66];
    const int tid = threadIdx.x;
    {
        const int r  = tid >> 2;
        const int cq = (tid & 3) * 16;
        const float* src = in + (kt * 64 + r) * C + ct * 64 + cq;
        #pragma unroll
        for (int u = 0; u < 16; u += 4) {
            float4 v = *(const float4*)(src + u);
            tile[r][cq + u + 0] = __float2half_rn(v.x);
            tile[r][cq + u + 1] = __float2half_rn(v.y);
            tile[r][cq + u + 2] = __float2half_rn(v.z);
            tile[r][cq + u + 3] = __float2half_rn(v.w);
        }
    }
    __syncthreads();
    {
        const int cc = tid >> 2;
        const int kq = (tid & 3) * 16;
        __half* dst = out + (ct * 64 + cc) * K_TOT + kt * 64 + kq;
        #pragma unroll
        for (int u = 0; u < 16; u += 2) {
            __half2 h = __halves2half2(tile[kq + u][cc], tile[kq + u + 1][cc]);
            *(uint32_t*)(dst + u) = *(uint32_t*)&h;
        }
    }
}

__global__ void __launch_bounds__(256)
transpose_traces_kernel()
{
    const int bid = blockIdx.x;
    if (bid < 800) transpose_tile_h2h(g_pre_tr_h,  g_pre_trT,  NIN,  bid >> 4, bid & 15);
    else { int b = bid - 800; transpose_tile_h2h(g_post_tr_h, g_post_trT, NOUT, b >> 3, b & 7); }
}

__global__ void __launch_bounds__(256)
transpose_spikes_kernel(const float* __restrict__ pre_spikes,
                        const float* __restrict__ post_spikes)
{
    const int bid = blockIdx.x;
    if (bid < 800) transpose_tile_f2h(pre_spikes,  g_pre_sT,  NIN,  bid >> 4, bid & 15);
    else { int b = bid - 800; transpose_tile_f2h(post_spikes, g_post_sT, NOUT, b >> 3, b & 7); }
}

// ============================ 3) Dual GEMM (wmma/HMMA) =====================
// 128 CTAs: bid = gemm(1b) | split(1b) | mtile(2b) | ntile(3b).
// GEMM0 (LTP): D[o,i] = sum_k post_sT[o,k] * pre_trT[i,k]
// GEMM1 (LTD): D[o,i] = sum_k post_trT[o,k] * pre_sT[i,k]
// CTA tile 128x128, BK=64, double-buffered smem (72-half rows), 8 warps in
// 2x4, each warp 64x32 via 4x2 wmma 16x16x16 f16->f32 fragments.
#define KSPLIT  1600
#define BK      64
#define NCHUNKS (KSPLIT / BK)     // 25
#define LDS     72                // padded halves per smem row (144B, %16B==0)
#define TILE_HALVES (128 * LDS)   // 9216
#define GEMM_SMEM (4 * TILE_HALVES * 2)   // A/B x 2 buffers x 2B = 73728

__global__ void __launch_bounds__(256)
stdp_gemm_kernel()
{
    extern __shared__ __align__(16) __half smem[];
    __half* smA[2] = { smem,                   smem + 2 * TILE_HALVES };
    __half* smB[2] = { smem + TILE_HALVES,     smem + 3 * TILE_HALVES };

    const int tid = threadIdx.x;
    const int wid = tid >> 5;
    const int bid = blockIdx.x;
    const int gm  = bid >> 6;
    const int sp  = (bid >> 5) & 1;
    const int mt  = (bid >> 3) & 3;
    const int nt  = bid & 7;

    const __half* Ap = gm ? g_post_trT : g_post_sT;   // [o, k]
    const __half* Bp = gm ? g_pre_sT   : g_pre_trT;   // [i, k]
    const int m0 = mt * 128, n0 = nt * 128, kb = sp * KSPLIT;

    const int lrow = tid >> 1;          // 0..127
    const int lcol = (tid & 1) * 32;    // half-block within BK=64

    wmma::fragment<wmma::accumulator, 16, 16, 16, float> acc[4][2];
    #pragma unroll
    for (int am = 0; am < 4; ++am)
        #pragma unroll
        for (int bn = 0; bn < 2; ++bn)
            wmma::fill_fragment(acc[am][bn], 0.0f);

    const int wm = (wid >> 2) * 64;     // warp row offset (0/64)
    const int wn = (wid & 3) * 32;      // warp col offset (0/32/64/96)

    // Prologue: load chunk 0 into buffer 0
    {
        const __half* sa = Ap + (m0 + lrow) * K_TOT + kb + lcol;
        const __half* sb = Bp + (n0 + lrow) * K_TOT + kb + lcol;
        #pragma unroll
        for (int q = 0; q < 4; ++q) {
            *(uint4*)&smA[0][lrow * LDS + lcol + q * 8] = *(const uint4*)(sa + q * 8);
            *(uint4*)&smB[0][lrow * LDS + lcol + q * 8] = *(const uint4*)(sb + q * 8);
        }
    }
    __syncthreads();

    for (int c = 0; c < NCHUNKS; ++c) {
        const int cur = c & 1;
        // Prefetch next chunk into registers (overlaps with compute)
        uint4 ra[4], rb[4];
        if (c + 1 < NCHUNKS) {
            const __half* sa = Ap + (m0 + lrow) * K_TOT + kb + (c + 1) * BK + lcol;
            const __half* sb = Bp + (n0 + lrow) * K_TOT + kb + (c + 1) * BK + lcol;
            #pragma unroll
            for (int q = 0; q < 4; ++q) {
                ra[q] = *(const uint4*)(sa + q * 8);
                rb[q] = *(const uint4*)(sb + q * 8);
            }
        }
        // Compute on current buffer
        #pragma unroll
        for (int kk = 0; kk < BK / 16; ++kk) {
            wmma::fragment<wmma::matrix_a, 16, 16, 16, __half, wmma::row_major> af[4];
            wmma::fragment<wmma::matrix_b, 16, 16, 16, __half, wmma::col_major> bf[2];
            #pragma unroll
            for (int am = 0; am < 4; ++am)
                wmma::load_matrix_sync(af[am], &smA[cur][(wm + am * 16) * LDS + kk * 16], LDS);
            #pragma unroll
            for (int bn = 0; bn < 2; ++bn)
                wmma::load_matrix_sync(bf[bn], &smB[cur][(wn + bn * 16) * LDS + kk * 16], LDS);
            #pragma unroll
            for (int am = 0; am < 4; ++am)
                #pragma unroll
                for (int bn = 0; bn < 2; ++bn)
                    wmma::mma_sync(acc[am][bn], af[am], bf[bn], acc[am][bn]);
        }
        __syncthreads();
        if (c + 1 < NCHUNKS) {
            const int nxt = cur ^ 1;
            #pragma unroll
            for (int q = 0; q < 4; ++q) {
                *(uint4*)&smA[nxt][lrow * LDS + lcol + q * 8] = ra[q];
                *(uint4*)&smB[nxt][lrow * LDS + lcol + q * 8] = rb[q];
            }
            __syncthreads();
        }
    }

    // Epilogue: store fragments to the partial buffer (row-major [o, i])
    float* dst = &g_part[gm * 2 + sp][0];
    #pragma unroll
    for (int am = 0; am < 4; ++am)
        #pragma unroll
        for (int bn = 0; bn < 2; ++bn)
            wmma::store_matrix_sync(
                dst + (m0 + wm + am * 16) * NIN + n0 + wn + bn * 16,
                acc[am][bn], NIN, wmma::mem_row_major);
}

// ============================ 4) Combine ===================================
// delta_w = s*((1-w)*(P0+P1) - w*(D0+D1)), all [o,i] row-major, coalesced.
__global__ void __launch_bounds__(256)
combine_kernel(const float* __restrict__ weight,
               float* __restrict__ delta_w)
{
    const float s = LR_LTP / (float)BATCH;
    const int idx = (blockIdx.x * 256 + threadIdx.x) * 8;
    #pragma unroll
    for (int h = 0; h < 2; ++h) {
        const int a = idx + h * 4;
        float4 w  = *(const float4*)(weight + a);
        float4 p0 = *(const float4*)(&g_part[0][a]);
        float4 p1 = *(const float4*)(&g_part[1][a]);
        float4 d0 = *(const float4*)(&g_part[2][a]);
        float4 d1 = *(const float4*)(&g_part[3][a]);
        float4 r;
        r.x = s * ((1.f - w.x) * (p0.x + p1.x) - w.x * (d0.x + d1.x));
        r.y = s * ((1.f - w.y) * (p0.y + p1.y) - w.y * (d0.y + d1.y));
        r.z = s * ((1.f - w.z) * (p0.z + p1.z) - w.z * (d0.z + d1.z));
        r.w = s * ((1.f - w.w) * (p0.w + p1.w) - w.w * (d0.w + d1.w));
        *(float4*)(delta_w + a) = r;
    }
}

// ===========================================================================
extern "C" void kernel_launch(void* const* d_in, const int* in_sizes, int n_in,
                              void* d_out, int out_size)
{
    const float* weight      = (const float*)d_in[0];  // [NOUT, NIN]
    const float* pre_spikes  = (const float*)d_in[1];  // [T, B, NIN]
    const float* post_spikes = (const float*)d_in[2];  // [T, B, NOUT]
    const float* pre_trace0  = (const float*)d_in[3];  // [B, NIN]
    const float* post_trace0 = (const float*)d_in[4];  // [B, NOUT]

    float* out         = (float*)d_out;
    float* out_delta_w = out;                              // 512*1024
    float* out_pre_tr  = out + NOUT * NIN;                 // 32*1024
    float* out_post_tr = out + NOUT * NIN + BATCH * NIN;   // 32*512

    cudaFuncSetAttribute(stdp_gemm_kernel,
                         cudaFuncAttributeMaxDynamicSharedMemorySize, GEMM_SMEM);

    // 1) Traces (fp16 history [k,col] + exact fp32 final traces)
    traces_fused_kernel<<<PRE_CTAS + POST_CTAS, 256>>>(
        pre_spikes, post_spikes, pre_trace0, post_trace0,
        out_pre_tr, out_post_tr);

    // 2) K-major fp16 operands: spikes (fp32->fp16) and trace history
    transpose_spikes_kernel<<<1200, 256>>>(pre_spikes, post_spikes);
    transpose_traces_kernel<<<1200, 256>>>();

    // 3) Dual wmma/HMMA f16 GEMM, split-K=2, 128 CTAs
    stdp_gemm_kernel<<<128, 256, GEMM_SMEM>>>();

    // 4) Combine partials + soft-bound epilogue
    combine_kernel<<<(NOUT * NIN / 8) / 256, 256>>>(weight, out_delta_w);
}

// round 14
// speedup vs baseline: 1.9128x; 1.9128x over previous
#include <cuda_runtime.h>
#include <cuda_fp16.h>
#include <cstdint>

// Problem constants (match reference)
#define T_STEPS 100
#define BATCH   32
#define NIN     1024
#define NOUT    512
#define K_TOT   3200

#define LR_LTP  1e-4f
#define DECAY      0.951229424500714f    // exp(-1/20)
#define INV_DECAY  1.0512710963760241f   // exp(+1/20)
#define D49        0.0862935864993704f   // exp(-49/20)
#define D50        0.0820849986238988f   // exp(-50/20)

// Device scratch (allocation-free). All [k, col] natural layouts.
__device__ __align__(16) __half g_pre_tr_h [K_TOT * NIN];   // [k, i] traces
__device__ __align__(16) __half g_post_tr_h[K_TOT * NOUT];  // [k, o]
__device__ __align__(16) __half g_pre_s16  [K_TOT * NIN];   // [k, i] fp16 spikes
__device__ __align__(16) __half g_post_s16 [K_TOT * NOUT];  // [k, o]
__device__ __align__(16) float  g_part[8][NOUT * NIN];      // [gemm*4+split]

// ============================ 1) Traces ====================================
// T chunked in 2 with dot-product carry (R10); ALSO stores fp16 spikes so the
// GEMM consumes natural [k,col] layouts (no transpose kernels).
#define PRE_CTAS  ((2 * BATCH * NIN ) / 256)   // 256
#define POST_CTAS ((2 * BATCH * NOUT) / 256)   // 128
#define UB 10

__global__ void __launch_bounds__(256)
traces_fused_kernel(const float* __restrict__ pre_spikes,
                    const float* __restrict__ post_spikes,
                    const float* __restrict__ pre_trace0,
                    const float* __restrict__ post_trace0,
                    float* __restrict__ out_pre_tr,
                    float* __restrict__ out_post_tr)
{
    if (blockIdx.x < PRE_CTAS) {
        const int g   = blockIdx.x * 256 + threadIdx.x;
        const int c   = g >> 15;
        const int idx = g & 32767;               // b*NIN + i
        float tr;
        if (c == 0) {
            tr = pre_trace0[idx];
            for (int t0 = 0; t0 < 50; t0 += UB) {
                float s[UB];
                #pragma unroll
                for (int u = 0; u < UB; ++u)
                    s[u] = __ldcs(&pre_spikes[(t0 + u) * (BATCH * NIN) + idx]);
                #pragma unroll
                for (int u = 0; u < UB; ++u) {
                    const int a = (t0 + u) * (BATCH * NIN) + idx;
                    tr = tr * DECAY + s[u];
                    g_pre_tr_h[a] = __float2half_rn(tr);
                    g_pre_s16[a]  = __float2half_rn(s[u]);
                }
            }
        } else {
            float acc0 = 0.f, acc1 = 0.f, w = D49;
            for (int t0 = 0; t0 < 50; t0 += UB) {
                float s[UB];
                #pragma unroll
                for (int u = 0; u < UB; ++u)
                    s[u] = __ldcs(&pre_spikes[(t0 + u) * (BATCH * NIN) + idx]);
                #pragma unroll
                for (int u = 0; u < UB; ++u) {
                    if (u & 1) acc1 = fmaf(w, s[u], acc1);
                    else       acc0 = fmaf(w, s[u], acc0);
                    w *= INV_DECAY;
                }
            }
            tr = fmaf(D50, pre_trace0[idx], acc0 + acc1);
            for (int t0 = 50; t0 < 100; t0 += UB) {
                float s[UB];
                #pragma unroll
                for (int u = 0; u < UB; ++u)
                    s[u] = __ldcs(&pre_spikes[(t0 + u) * (BATCH * NIN) + idx]);
                #pragma unroll
                for (int u = 0; u < UB; ++u) {
                    const int a = (t0 + u) * (BATCH * NIN) + idx;
                    tr = tr * DECAY + s[u];
                    g_pre_tr_h[a] = __float2half_rn(tr);
                    g_pre_s16[a]  = __float2half_rn(s[u]);
                }
            }
            out_pre_tr[idx] = tr;
        }
    } else {
        const int g   = (blockIdx.x - PRE_CTAS) * 256 + threadIdx.x;
        const int c   = g >> 14;
        const int idx = g & 16383;               // b*NOUT + o
        float tr;
        if (c == 0) {
            tr = post_trace0[idx];
            for (int t0 = 0; t0 < 50; t0 += UB) {
                float s[UB];
                #pragma unroll
                for (int u = 0; u < UB; ++u)
                    s[u] = __ldcs(&post_spikes[(t0 + u) * (BATCH * NOUT) + idx]);
                #pragma unroll
                for (int u = 0; u < UB; ++u) {
                    const int a = (t0 + u) * (BATCH * NOUT) + idx;
                    tr = tr * DECAY + s[u];
                    g_post_tr_h[a] = __float2half_rn(tr);
                    g_post_s16[a]  = __float2half_rn(s[u]);
                }
            }
        } else {
            float acc0 = 0.f, acc1 = 0.f, w = D49;
            for (int t0 = 0; t0 < 50; t0 += UB) {
                float s[UB];
                #pragma unroll
                for (int u = 0; u < UB; ++u)
                    s[u] = __ldcs(&post_spikes[(t0 + u) * (BATCH * NOUT) + idx]);
                #pragma unroll
                for (int u = 0; u < UB; ++u) {
                    if (u & 1) acc1 = fmaf(w, s[u], acc1);
                    else       acc0 = fmaf(w, s[u], acc0);
                    w *= INV_DECAY;
                }
            }
            tr = fmaf(D50, post_trace0[idx], acc0 + acc1);
            for (int t0 = 50; t0 < 100; t0 += UB) {
                float s[UB];
                #pragma unroll
                for (int u = 0; u < UB; ++u)
                    s[u] = __ldcs(&post_spikes[(t0 + u) * (BATCH * NOUT) + idx]);
                #pragma unroll
                for (int u = 0; u < UB; ++u) {
                    const int a = (t0 + u) * (BATCH * NOUT) + idx;
                    tr = tr * DECAY + s[u];
                    g_post_tr_h[a] = __float2half_rn(tr);
                    g_post_s16[a]  = __float2half_rn(s[u]);
                }
            }
            out_post_tr[idx] = tr;
        }
    }
}

// ============================ 2) GEMM (mma.sync) ===========================
// D[m,n] = sum_k A[k,m] * B[k,n];  A = post [k,NOUT], B = pre [k,NIN].
// GEMM0 (LTP): A=post_s16, B=pre_tr.  GEMM1 (LTD): A=post_tr, B=pre_s16.
// 256 CTAs: gemm(1b) | split(2b,=4) | mt(2b) | nt(3b). CTA tile 128x128,
// BK=32, 3-stage cp.async pipeline, 8 warps (2x4), warp tile 64x32.
#define KSPLIT   800
#define BK       32
#define NCHUNKS  (KSPLIT / BK)    // 25
#define LDT      136              // halves per smem row (272B: %16B==0, 8-row
                                  // ldmatrix addrs cover all 32 banks)
#define TILE_B2  (BK * LDT * 2)   // 8704 bytes per operand tile
#define STAGE_B  (2 * TILE_B2)    // 17408 bytes (A + B)
#define NSTAGE   3
#define GEMM_SMEM (NSTAGE * STAGE_B)   // 52224

__device__ __forceinline__ uint32_t smem_u32(const void* p) {
    uint32_t a;
    asm("{ .reg .u64 t; cvta.to.shared.u64 t, %1; cvt.u32.u64 %0, t; }"
        : "=r"(a) : "l"(p));
    return a;
}
#define CP_ASYNC16(dst, src) \
    asm volatile("cp.async.cg.shared.global [%0], [%1], 16;" :: "r"(dst), "l"(src))
#define CP_COMMIT() asm volatile("cp.async.commit_group;" ::: "memory")
#define CP_WAIT2()  asm volatile("cp.async.wait_group 2;" ::: "memory")

// ldmatrix x4 transposed (both operands stored [k, col]).
#define LDMATRIX_X4_T(r0, r1, r2, r3, addr) \
    asm volatile("ldmatrix.sync.aligned.m8n8.x4.trans.shared.b16 {%0,%1,%2,%3}, [%4];" \
        : "=r"(r0), "=r"(r1), "=r"(r2), "=r"(r3) : "r"(addr))

#define MMA16816(d0, d1, d2, d3, a0, a1, a2, a3, b0, b1) \
    asm volatile("mma.sync.aligned.m16n8k16.row.col.f32.f16.f16.f32 " \
        "{%0,%1,%2,%3}, {%4,%5,%6,%7}, {%8,%9}, {%0,%1,%2,%3};" \
        : "+f"(d0), "+f"(d1), "+f"(d2), "+f"(d3) \
        : "r"(a0), "r"(a1), "r"(a2), "r"(a3), "r"(b0), "r"(b1))

__global__ void __launch_bounds__(256, 2)
stdp_gemm_kernel()
{
    extern __shared__ __align__(16) char smem[];
    const uint32_t sbase = smem_u32(smem);

    const int tid  = threadIdx.x;
    const int wid  = tid >> 5;
    const int lane = tid & 31;
    const int bid  = blockIdx.x;
    const int gm   = bid >> 7;
    const int sp   = (bid >> 5) & 3;
    const int mt   = (bid >> 3) & 3;
    const int nt   = bid & 7;

    const __half* Ap = gm ? g_post_tr_h : g_post_s16;   // [k, NOUT]
    const __half* Bp = gm ? g_pre_s16   : g_pre_tr_h;   // [k, NIN]
    const int m0 = mt * 128, n0 = nt * 128, kb = sp * KSPLIT;

    // Loader mapping: row = tid>>3 (32 k-rows), 8 threads x 16B, 2 passes.
    const int lrow = tid >> 3;
    const int lc0  = (tid & 7) * 8;    // halves

    auto issue_chunk = [&](int c, int stage) {
        const int krow = kb + c * BK + lrow;
        const uint32_t dA = sbase + stage * STAGE_B + lrow * (LDT * 2) + lc0 * 2;
        const uint32_t dB = dA + TILE_B2;
        const __half* sa = Ap + (size_t)krow * NOUT + m0 + lc0;
        const __half* sb = Bp + (size_t)krow * NIN  + n0 + lc0;
        CP_ASYNC16(dA,           sa);
        CP_ASYNC16(dA + 128,     sa + 64);   // +64 halves
        CP_ASYNC16(dB,           sb);
        CP_ASYNC16(dB + 128,     sb + 64);
    };

    // Warp tiling: 2 (m) x 4 (n); warp tile 64 x 32.
    const int wm = (wid & 1) * 64;
    const int wn = (wid >> 1) * 32;
    const int r  = lane & 7;
    const int j  = lane >> 3;

    float acc[4][4][4];   // [mi 16][ni 8][d0..d3]
    #pragma unroll
    for (int mi = 0; mi < 4; ++mi)
        #pragma unroll
        for (int ni = 0; ni < 4; ++ni)
            #pragma unroll
            for (int q = 0; q < 4; ++q) acc[mi][ni][q] = 0.f;

    // Prologue: 3 stages in flight
    issue_chunk(0, 0); CP_COMMIT();
    issue_chunk(1, 1); CP_COMMIT();
    issue_chunk(2, 2); CP_COMMIT();

    for (int c = 0; c < NCHUNKS; ++c) {
        CP_WAIT2();            // chunk c resident
        __syncthreads();
        const uint32_t tA = sbase + (c % NSTAGE) * STAGE_B;
        const uint32_t tB = tA + TILE_B2;

        #pragma unroll
        for (int kk = 0; kk < BK / 16; ++kk) {
            const int k0 = kk * 16;
            // A fragments (m16k16 each, from [k][m] via ldmatrix.trans):
            //   block j: rows k0 + (j>>1)*8 + r, cols mf + (j&1)*8
            uint32_t a[4][4];
            #pragma unroll
            for (int mi = 0; mi < 4; ++mi) {
                const int mf = wm + mi * 16;
                const uint32_t ad = tA + (uint32_t)(k0 + (j >> 1) * 8 + r) * (LDT * 2)
                                       + (uint32_t)(mf + (j & 1) * 8) * 2;
                LDMATRIX_X4_T(a[mi][0], a[mi][1], a[mi][2], a[mi][3], ad);
            }
            // B fragments (two k16n8 per x4, from [k][n]):
            //   block j: rows k0 + (j&1)*8 + r, cols nf + (j>>1)*8
            uint32_t b[4][2];
            #pragma unroll
            for (int nj = 0; nj < 2; ++nj) {
                const int nf = wn + nj * 16;
                const uint32_t bd = tB + (uint32_t)(k0 + (j & 1) * 8 + r) * (LDT * 2)
                                       + (uint32_t)(nf + (j >> 1) * 8) * 2;
                uint32_t r0, r1, r2, r3;
                LDMATRIX_X4_T(r0, r1, r2, r3, bd);
                b[nj * 2 + 0][0] = r0; b[nj * 2 + 0][1] = r1;
                b[nj * 2 + 1][0] = r2; b[nj * 2 + 1][1] = r3;
            }
            #pragma unroll
            for (int mi = 0; mi < 4; ++mi)
                #pragma unroll
                for (int ni = 0; ni < 4; ++ni)
                    MMA16816(acc[mi][ni][0], acc[mi][ni][1], acc[mi][ni][2], acc[mi][ni][3],
                             a[mi][0], a[mi][1], a[mi][2], a[mi][3],
                             b[ni][0], b[ni][1]);
        }
        __syncthreads();
        if (c + 3 < NCHUNKS) issue_chunk(c + 3, c % NSTAGE);
        CP_COMMIT();
    }

    // Epilogue: D thread map: d0,d1 = (g, 2c'..+1), d2,d3 = (g+8, 2c'..+1)
    const int dg = lane >> 2;
    const int dc = (lane & 3) * 2;
    float* dst = &g_part[gm * 4 + sp][0];
    #pragma unroll
    for (int mi = 0; mi < 4; ++mi)
        #pragma unroll
        for (int ni = 0; ni < 4; ++ni) {
            const int row = m0 + wm + mi * 16 + dg;
            const int col = n0 + wn + ni * 8 + dc;
            *(float2*)&dst[(size_t)row * NIN + col] =
                make_float2(acc[mi][ni][0], acc[mi][ni][1]);
            *(float2*)&dst[(size_t)(row + 8) * NIN + col] =
                make_float2(acc[mi][ni][2], acc[mi][ni][3]);
        }
}

// ============================ 3) Combine ===================================
// delta_w = s*((1-w)*sum(P) - w*sum(D)) over 4 split partials each.
__global__ void __launch_bounds__(256)
combine_kernel(const float* __restrict__ weight,
               float* __restrict__ delta_w)
{
    const float s = LR_LTP / (float)BATCH;
    const int idx = (blockIdx.x * 256 + threadIdx.x) * 4;
    float4 w = *(const float4*)(weight + idx);
    float4 p = *(const float4*)(&g_part[0][idx]);
    float4 d = *(const float4*)(&g_part[4][idx]);
    #pragma unroll
    for (int q = 1; q < 4; ++q) {
        float4 pq = *(const float4*)(&g_part[q][idx]);
        float4 dq = *(const float4*)(&g_part[4 + q][idx]);
        p.x += pq.x; p.y += pq.y; p.z += pq.z; p.w += pq.w;
        d.x += dq.x; d.y += dq.y; d.z += dq.z; d.w += dq.w;
    }
    float4 r;
    r.x = s * ((1.f - w.x) * p.x - w.x * d.x);
    r.y = s * ((1.f - w.y) * p.y - w.y * d.y);
    r.z = s * ((1.f - w.z) * p.z - w.z * d.z);
    r.w = s * ((1.f - w.w) * p.w - w.w * d.w);
    *(float4*)(delta_w + idx) = r;
}

// ===========================================================================
extern "C" void kernel_launch(void* const* d_in, const int* in_sizes, int n_in,
                              void* d_out, int out_size)
{
    const float* weight      = (const float*)d_in[0];  // [NOUT, NIN]
    const float* pre_spikes  = (const float*)d_in[1];  // [T, B, NIN]
    const float* post_spikes = (const float*)d_in[2];  // [T, B, NOUT]
    const float* pre_trace0  = (const float*)d_in[3];  // [B, NIN]
    const float* post_trace0 = (const float*)d_in[4];  // [B, NOUT]

    float* out         = (float*)d_out;
    float* out_delta_w = out;                              // 512*1024
    float* out_pre_tr  = out + NOUT * NIN;                 // 32*1024
    float* out_post_tr = out + NOUT * NIN + BATCH * NIN;   // 32*512

    cudaFuncSetAttribute(stdp_gemm_kernel,
                         cudaFuncAttributeMaxDynamicSharedMemorySize, GEMM_SMEM);

    // 1) Traces + fp16 spike conversion (natural [k,col] layouts, no transposes)
    traces_fused_kernel<<<PRE_CTAS + POST_CTAS, 256>>>(
        pre_spikes, post_spikes, pre_trace0, post_trace0,
        out_pre_tr, out_post_tr);

    // 2) Dual f16 GEMM via mma.sync + ldmatrix + cp.async, split-K=4
    stdp_gemm_kernel<<<256, 256, GEMM_SMEM>>>();

    // 3) Combine 8 partials + soft-bound epilogue
    combine_kernel<<<(NOUT * NIN / 4) / 256, 256>>>(weight, out_delta_w);
}